// round 9
// baseline (speedup 1.0000x reference)
#include <cuda_runtime.h>
#include <cuda_bf16.h>

#define Bv 64
#define Tv 100
#define Av 8732
typedef unsigned long long ull;

// per-(b,t) packed winner: (q_bits << 32) | (0xFFFFFFFF - anchor)
__device__ ull   g_key[Bv * Tv];
// per-(b,t) prepass filter slope, pre-multiplied by 4 (for folded compare)
__device__ float g_slope4[Bv * Tv];

// safe reject-filter slope for quotient q: never rejects q' >= q
__device__ __forceinline__ float slope_of(float q) {
    return __fmul_rn(__fdividef(q, __fadd_rn(1.f, q)), 0.99999f);
}

// K0 (prepass): one warp per (b,t). Lanes read CONTIGUOUS 32-anchor chunks
// (coalesced float4, software-pipelined prefetch), chunks strided 16 apart
// (1/16 subset). shfl-max -> safe per-t filter slope. Also zeroes g_key.
// Grid: Bv*Tv/8 = 800, block 256.
__global__ __launch_bounds__(256) void k_pre(
        const float* __restrict__ targets,
        const float* __restrict__ anchors) {
    const int wg   = blockIdx.x * 8 + (threadIdx.x >> 5);   // 0..6399
    const int lane = threadIdx.x & 31;
    const int b = wg / Tv, t = wg % Tv;

    const float* tp = targets + ((size_t)b * Tv + t) * 5;
    float x1 = tp[0], y1 = tp[1], x2 = tp[2], y2 = tp[3];
    float area = __fmul_rn(__fsub_rn(x2, x1), __fsub_rn(y2, y1));

    const int NCHUNK = (Av + 31) / 32;        // 273 chunks of 32 anchors
    float qmax = 0.f;

    int c = t & 15;
    int a = c * 32 + lane;
    float4 cur = make_float4(0.f, 0.f, 0.f, 0.f);
    bool curv = (c < NCHUNK) && (a < Av);
    if (curv) cur = __ldg((const float4*)anchors + a);

    while (c < NCHUNK) {
        int cn = c + 16;                       // prefetch next chunk
        int an_i = cn * 32 + lane;
        float4 nxt = make_float4(0.f, 0.f, 0.f, 0.f);
        bool nv = (cn < NCHUNK) && (an_i < Av);
        if (nv) nxt = __ldg((const float4*)anchors + an_i);

        if (curv) {
            float hw = cur.z * 0.5f, hh = cur.w * 0.5f;
            float dx = fminf(x2, cur.x + hw) - fmaxf(x1, cur.x - hw);
            float dy = fminf(y2, cur.y + hh) - fmaxf(y1, cur.y - hh);
            if (dx > 0.f && dy > 0.f) {
                float inter = dx * dy;
                float q = __fdividef(inter, area + cur.z * cur.w - inter);
                qmax = fmaxf(qmax, q);
            }
        }
        cur = nxt; curv = nv; c = cn;
    }
#pragma unroll
    for (int off = 16; off; off >>= 1)
        qmax = fmaxf(qmax, __shfl_xor_sync(0xffffffffu, qmax, off));

    if (lane == 0) {
        g_key[wg] = 0ull;
        float qlb = qmax * 0.999f;
        g_slope4[wg] = (qlb > 0.f) ? __fmul_rn(slope_of(qlb), 4.f) : 0.f;
    }
}

// K1 (fused): one pass over all (b,t,a) IoUs, both argmax reductions, AND the
// non-forced epilogue, written straight to out.
// Per-anchor argmax is BRANCHLESS (cross-multiplied compare + predicated
// selects + sticky ambiguity flag resolved exactly post-loop). Per-t candidate
// path is warp-voted (slp_t from prepass makes it ~1% of warp-iterations).
// Grid: (ceil(A/256), B), block 256. Thread = one anchor; loop over t.
__global__ __launch_bounds__(256) void k_fused(
        const float* __restrict__ targets,
        const float* __restrict__ anchors,
        float* __restrict__ out) {
    __shared__ float4 sbox[Tv];
    __shared__ float2 saux[Tv];   // x = area, y = slp4 (fixed per t)
    __shared__ float  slab[Tv];
    __shared__ ull    skey[Tv];

    const int b   = blockIdx.y;
    const int tid = threadIdx.x;
    if (tid < Tv) {
        const float* tp = targets + ((size_t)b * Tv + tid) * 5;
        float x1 = tp[0], y1 = tp[1], x2 = tp[2], y2 = tp[3];
        sbox[tid] = make_float4(x1, y1, x2, y2);
        saux[tid] = make_float2(__fmul_rn(__fsub_rn(x2, x1), __fsub_rn(y2, y1)),
                                g_slope4[b * Tv + tid]);
        slab[tid] = tp[4];
        skey[tid] = 0ull;
    }
    __syncthreads();

    const int a0 = blockIdx.x * 256 + tid;
    const int a  = min(a0, Av - 1);          // clamped lanes duplicate a=Av-1 (harmless)

    float4 an = __ldg((const float4*)anchors + a);
    float hw  = __fmul_rn(an.z, 0.5f), hh = __fmul_rn(an.w, 0.5f);
    float ax1 = __fsub_rn(an.x, hw),  ay1 = __fsub_rn(an.y, hh);
    float ax2 = __fadd_rn(an.x, hw),  ay2 = __fadd_rn(an.y, hh);
    float aa  = __fmul_rn(__fsub_rn(ax2, ax1), __fsub_rn(ay2, ay1));

    float pr_b = 0.f, sab_b = 1.f; int t_b = 0;
    bool amb = false;
#pragma unroll 4
    for (int t = 0; t < Tv; t++) {
        float4 bx = sbox[t];
        float2 ax = saux[t];
        // pr = 4*inter exactly; 0.5-scales folded out (pow2 scaling is exact)
        float ux = __fsub_rn(fminf(bx.z, ax2), fmaxf(bx.x, ax1));
        float uy = __fsub_rn(fminf(bx.w, ay2), fmaxf(bx.y, ay1));
        float px = __fadd_rn(ux, fabsf(ux));
        float py = __fadd_rn(uy, fabsf(uy));
        float pr = __fmul_rn(px, py);
        float sab = __fadd_rn(ax.x, aa);

        // branchless per-anchor argmax: cross-multiplied ratio compare.
        float pn = __fmul_rn(pr, sab_b);
        float pc = __fmul_rn(pr_b, sab);
        // ambiguity band 2e-6 rel: superset of all rounded-quotient ties
        amb |= (pc > 0.f) &&
               (fabsf(__fsub_rn(pn, pc)) <= __fmul_rn(pc, 2e-6f));
        if (pn > pc) { pr_b = pr; sab_b = sab; t_b = t; }   // predicated SELs

        // per-t candidate (safe prepass filter); warp-voted rare path
        bool cand = pr > __fmul_rn(ax.y, sab);
        if (__any_sync(0xffffffffu, cand)) {
            if (cand) {
                float inter = __fmul_rn(pr, 0.25f);
                float qc = __fdiv_rn(inter, __fsub_rn(sab, inter));  // exact IoU
                ull key = ((ull)__float_as_uint(qc) << 32)
                        | (unsigned)(0xFFFFFFFFu - (unsigned)a);
                atomicMax(&skey[t], key);                    // tie -> lowest a
            }
        }
    }

    // resolve per-anchor winner exactly
    float q; int ct;
    if (amb) {                         // rare: exact rescan, first-max wins
        q = 0.f; ct = 0;
        for (int t = 0; t < Tv; t++) {
            float4 bx = sbox[t];
            float ux = __fsub_rn(fminf(bx.z, ax2), fmaxf(bx.x, ax1));
            float uy = __fsub_rn(fminf(bx.w, ay2), fmaxf(bx.y, ay1));
            float px = __fadd_rn(ux, fabsf(ux));
            float py = __fadd_rn(uy, fabsf(uy));
            float pr = __fmul_rn(px, py);
            float sab = __fadd_rn(saux[t].x, aa);
            float inter = __fmul_rn(pr, 0.25f);
            float qc = __fdiv_rn(inter, __fsub_rn(sab, inter));
            if (qc > q) { q = qc; ct = t; }
        }
    } else {
        ct = t_b;
        float inter = __fmul_rn(pr_b, 0.25f);
        q = __fdiv_rn(inter, __fsub_rn(sab_b, inter));   // 0/1=0 for empty rows
    }

    if (a0 < Av) {                     // non-forced epilogue (patched later)
        int conf = (q < 0.5f) ? 0 : ((int)slab[ct] + 1);
        float4 m  = sbox[ct];
        float mcx = (m.x + m.z) * 0.5f, mcy = (m.y + m.w) * 0.5f;
        float mw  = m.z - m.x,          mh  = m.w - m.y;
        float l0  = (mcx - an.x) / (0.1f * an.z);
        float l1  = (mcy - an.y) / (0.1f * an.w);
        float l2  = logf(mw / an.z) / 0.2f;
        float l3  = logf(mh / an.w) / 0.2f;
        ((float4*)out)[(size_t)b * Av + a0] = make_float4(l0, l1, l2, l3);
        out[(size_t)Bv * Av * 4 + (size_t)b * Av + a0] = (float)conf;
    }

    __syncthreads();
    if (tid < Tv && skey[tid])
        atomicMax(&g_key[b * Tv + tid], skey[tid]);
}

// K2 (patch): apply forced matches. One block per b. smem arena resolves
// duplicate winner anchors with max-t (= last write wins). key==0 -> anchor 0
// (matches jnp.argmax of an all-zero row).
__global__ __launch_bounds__(128) void k_patch(
        const float* __restrict__ targets,
        const float* __restrict__ anchors,
        float* __restrict__ out) {
    __shared__ int    sa[Av];       // ~34.9 KB
    __shared__ float4 sbox[Tv];
    __shared__ float  slab[Tv];
    __shared__ int    swin[Tv];

    const int b = blockIdx.x, tid = threadIdx.x;
    for (int i = tid; i < Av; i += 128) sa[i] = -1;
    if (tid < Tv) {
        const float* tp = targets + ((size_t)b * Tv + tid) * 5;
        sbox[tid] = make_float4(tp[0], tp[1], tp[2], tp[3]);
        slab[tid] = tp[4];
        ull key = g_key[b * Tv + tid];
        swin[tid] = key ? (int)(0xFFFFFFFFu - (unsigned)key) : 0;
    }
    __syncthreads();
    if (tid < Tv) atomicMax(&sa[swin[tid]], tid);
    __syncthreads();
    if (tid < Tv) {
        int a = swin[tid];
        if (sa[a] == tid) {                      // this t owns anchor a
            float4 an = __ldg((const float4*)anchors + a);
            int conf = (int)slab[tid] + 1;       // overlap forced to 1.0
            float4 m  = sbox[tid];
            float mcx = (m.x + m.z) * 0.5f, mcy = (m.y + m.w) * 0.5f;
            float mw  = m.z - m.x,          mh  = m.w - m.y;
            float l0  = (mcx - an.x) / (0.1f * an.z);
            float l1  = (mcy - an.y) / (0.1f * an.w);
            float l2  = logf(mw / an.z) / 0.2f;
            float l3  = logf(mh / an.w) / 0.2f;
            ((float4*)out)[(size_t)b * Av + a] = make_float4(l0, l1, l2, l3);
            out[(size_t)Bv * Av * 4 + (size_t)b * Av + a] = (float)conf;
        }
    }
}

extern "C" void kernel_launch(void* const* d_in, const int* in_sizes, int n_in,
                              void* d_out, int out_size) {
    const float* targets = (const float*)d_in[0];   // (B, T, 5) f32
    const float* anchors = (const float*)d_in[1];   // (A, 4)   f32
    float* out = (float*)d_out;                     // loc (B*A*4) then conf (B*A)

    k_pre<<<(Bv * Tv) / 8, 256>>>(targets, anchors);

    dim3 g((Av + 255) / 256, Bv);
    k_fused<<<g, 256>>>(targets, anchors, out);

    k_patch<<<Bv, 128>>>(targets, anchors, out);
}

// round 10
// speedup vs baseline: 1.2443x; 1.2443x over previous
#include <cuda_runtime.h>
#include <cuda_bf16.h>

#define Bv 64
#define Tv 100
#define Av 8732
typedef unsigned long long ull;

// per-(b,t) packed winner: (q_bits << 32) | (0xFFFFFFFF - anchor)
__device__ ull   g_key[Bv * Tv];
// per-(b,t) prepass filter slope, pre-multiplied by 4 (for folded compare)
__device__ float g_slope4[Bv * Tv];

// safe reject-filter slope for quotient q: never rejects q' >= q
__device__ __forceinline__ float slope_of(float q) {
    return __fmul_rn(__fdividef(q, __fadd_rn(1.f, q)), 0.99999f);
}

// K0 (prepass): one warp per (b,t). Lanes read CONTIGUOUS 32-anchor chunks
// (coalesced float4, software-pipelined prefetch), chunks strided 32 apart
// (1/32 subset -- sampled max is a lower bound at any density, so the filter
// stays safe). shfl-max -> per-t filter slope. Also zeroes g_key.
// Grid: Bv*Tv/8 = 800, block 256.
__global__ __launch_bounds__(256) void k_pre(
        const float* __restrict__ targets,
        const float* __restrict__ anchors) {
    const int wg   = blockIdx.x * 8 + (threadIdx.x >> 5);   // 0..6399
    const int lane = threadIdx.x & 31;
    const int b = wg / Tv, t = wg % Tv;

    const float* tp = targets + ((size_t)b * Tv + t) * 5;
    float x1 = tp[0], y1 = tp[1], x2 = tp[2], y2 = tp[3];
    float area = __fmul_rn(__fsub_rn(x2, x1), __fsub_rn(y2, y1));

    const int NCHUNK = (Av + 31) / 32;        // 273 chunks of 32 anchors
    float qmax = 0.f;

    int c = t & 31;
    int a = c * 32 + lane;
    float4 cur = make_float4(0.f, 0.f, 0.f, 0.f);
    bool curv = (c < NCHUNK) && (a < Av);
    if (curv) cur = __ldg((const float4*)anchors + a);

    while (c < NCHUNK) {
        int cn = c + 32;                       // prefetch next chunk
        int an_i = cn * 32 + lane;
        float4 nxt = make_float4(0.f, 0.f, 0.f, 0.f);
        bool nv = (cn < NCHUNK) && (an_i < Av);
        if (nv) nxt = __ldg((const float4*)anchors + an_i);

        if (curv) {
            float hw = cur.z * 0.5f, hh = cur.w * 0.5f;
            float dx = fminf(x2, cur.x + hw) - fmaxf(x1, cur.x - hw);
            float dy = fminf(y2, cur.y + hh) - fmaxf(y1, cur.y - hh);
            if (dx > 0.f && dy > 0.f) {
                float inter = dx * dy;
                float q = __fdividef(inter, area + cur.z * cur.w - inter);
                qmax = fmaxf(qmax, q);
            }
        }
        cur = nxt; curv = nv; c = cn;
    }
#pragma unroll
    for (int off = 16; off; off >>= 1)
        qmax = fmaxf(qmax, __shfl_xor_sync(0xffffffffu, qmax, off));

    if (lane == 0) {
        g_key[wg] = 0ull;
        float qlb = qmax * 0.999f;
        g_slope4[wg] = (qlb > 0.f) ? __fmul_rn(slope_of(qlb), 4.f) : 0.f;
    }
}

// K1 (fused): one pass over all (b,t,a) IoUs, both argmax reductions, AND the
// non-forced epilogue (loc encode + conf, fast-math: tolerance 1e-3 vs ~1e-6
// error) written straight to out.
// Grid: (ceil(A/256), B), block 256. Thread = one anchor; loop over t.
__global__ __launch_bounds__(256) void k_fused(
        const float* __restrict__ targets,
        const float* __restrict__ anchors,
        float* __restrict__ out) {
    __shared__ float4 sbox[Tv];
    __shared__ float2 saux[Tv];   // x = area, y = slp4 (fixed per t)
    __shared__ float  slab[Tv];
    __shared__ ull    skey[Tv];

    const int b   = blockIdx.y;
    const int tid = threadIdx.x;
    if (tid < Tv) {
        const float* tp = targets + ((size_t)b * Tv + tid) * 5;
        float x1 = tp[0], y1 = tp[1], x2 = tp[2], y2 = tp[3];
        sbox[tid] = make_float4(x1, y1, x2, y2);
        saux[tid] = make_float2(__fmul_rn(__fsub_rn(x2, x1), __fsub_rn(y2, y1)),
                                g_slope4[b * Tv + tid]);
        slab[tid] = tp[4];
        skey[tid] = 0ull;
    }
    __syncthreads();

    const int a0 = blockIdx.x * 256 + tid;
    const int a  = min(a0, Av - 1);          // clamped lanes duplicate a=Av-1 (harmless)

    float4 an = __ldg((const float4*)anchors + a);
    float hw  = __fmul_rn(an.z, 0.5f), hh = __fmul_rn(an.w, 0.5f);
    float ax1 = __fsub_rn(an.x, hw),  ay1 = __fsub_rn(an.y, hh);
    float ax2 = __fadd_rn(an.x, hw),  ay2 = __fadd_rn(an.y, hh);
    float aa  = __fmul_rn(__fsub_rn(ax2, ax1), __fsub_rn(ay2, ay1));

    float q = 0.f, s4 = 0.f; int ct = 0;
#pragma unroll 5
    for (int t = 0; t < Tv; t++) {
        float4 bx = sbox[t];
        float2 ax = saux[t];
        // pr = 4*inter exactly; 0.5-scales folded out (pow2 scaling is exact)
        float ux = __fsub_rn(fminf(bx.z, ax2), fmaxf(bx.x, ax1));
        float uy = __fsub_rn(fminf(bx.w, ay2), fmaxf(bx.y, ay1));
        float px = __fadd_rn(ux, fabsf(ux));
        float py = __fadd_rn(uy, fabsf(uy));
        float pr = __fmul_rn(px, py);
        float sab = __fadd_rn(ax.x, aa);
        float m4  = fminf(s4, ax.y);
        if (pr > __fmul_rn(m4, sab)) {                        // rare path
            float inter = __fmul_rn(pr, 0.25f);               // exact
            float qc = __fdiv_rn(inter, __fsub_rn(sab, inter));   // exact IoU
            if (qc > q) {                                     // first-t wins
                q = qc; ct = t; s4 = __fmul_rn(slope_of(qc), 4.f);
            }
            if (pr > __fmul_rn(ax.y, sab)) {                  // per-t candidate
                ull key = ((ull)__float_as_uint(qc) << 32)
                        | (unsigned)(0xFFFFFFFFu - (unsigned)a);
                atomicMax(&skey[t], key);                     // tie -> lowest a
            }
        }
    }

    if (a0 < Av) {                     // non-forced epilogue (patched later)
        int conf = (q < 0.5f) ? 0 : ((int)slab[ct] + 1);
        float4 m  = sbox[ct];
        float mcx = (m.x + m.z) * 0.5f, mcy = (m.y + m.w) * 0.5f;
        float mw  = m.z - m.x,          mh  = m.w - m.y;
        float l0  = __fdividef(mcx - an.x, 0.1f * an.z);
        float l1  = __fdividef(mcy - an.y, 0.1f * an.w);
        float l2  = __logf(__fdividef(mw, an.z)) * 5.0f;
        float l3  = __logf(__fdividef(mh, an.w)) * 5.0f;
        ((float4*)out)[(size_t)b * Av + a0] = make_float4(l0, l1, l2, l3);
        out[(size_t)Bv * Av * 4 + (size_t)b * Av + a0] = (float)conf;
    }

    __syncthreads();
    if (tid < Tv && skey[tid])
        atomicMax(&g_key[b * Tv + tid], skey[tid]);
}

// K2 (patch): apply forced matches. One block per b. smem arena resolves
// duplicate winner anchors with max-t (= last write wins). key==0 -> anchor 0
// (matches jnp.argmax of an all-zero row). Exact math (tiny thread count).
__global__ __launch_bounds__(128) void k_patch(
        const float* __restrict__ targets,
        const float* __restrict__ anchors,
        float* __restrict__ out) {
    __shared__ int    sa[Av];       // ~34.9 KB
    __shared__ float4 sbox[Tv];
    __shared__ float  slab[Tv];
    __shared__ int    swin[Tv];

    const int b = blockIdx.x, tid = threadIdx.x;
    for (int i = tid; i < Av; i += 128) sa[i] = -1;
    if (tid < Tv) {
        const float* tp = targets + ((size_t)b * Tv + tid) * 5;
        sbox[tid] = make_float4(tp[0], tp[1], tp[2], tp[3]);
        slab[tid] = tp[4];
        ull key = g_key[b * Tv + tid];
        swin[tid] = key ? (int)(0xFFFFFFFFu - (unsigned)key) : 0;
    }
    __syncthreads();
    if (tid < Tv) atomicMax(&sa[swin[tid]], tid);
    __syncthreads();
    if (tid < Tv) {
        int a = swin[tid];
        if (sa[a] == tid) {                      // this t owns anchor a
            float4 an = __ldg((const float4*)anchors + a);
            int conf = (int)slab[tid] + 1;       // overlap forced to 1.0
            float4 m  = sbox[tid];
            float mcx = (m.x + m.z) * 0.5f, mcy = (m.y + m.w) * 0.5f;
            float mw  = m.z - m.x,          mh  = m.w - m.y;
            float l0  = (mcx - an.x) / (0.1f * an.z);
            float l1  = (mcy - an.y) / (0.1f * an.w);
            float l2  = logf(mw / an.z) / 0.2f;
            float l3  = logf(mh / an.w) / 0.2f;
            ((float4*)out)[(size_t)b * Av + a] = make_float4(l0, l1, l2, l3);
            out[(size_t)Bv * Av * 4 + (size_t)b * Av + a] = (float)conf;
        }
    }
}

extern "C" void kernel_launch(void* const* d_in, const int* in_sizes, int n_in,
                              void* d_out, int out_size) {
    const float* targets = (const float*)d_in[0];   // (B, T, 5) f32
    const float* anchors = (const float*)d_in[1];   // (A, 4)   f32
    float* out = (float*)d_out;                     // loc (B*A*4) then conf (B*A)

    k_pre<<<(Bv * Tv) / 8, 256>>>(targets, anchors);

    dim3 g((Av + 255) / 256, Bv);
    k_fused<<<g, 256>>>(targets, anchors, out);

    k_patch<<<Bv, 128>>>(targets, anchors, out);
}